// round 5
// baseline (speedup 1.0000x reference)
#include <cuda_runtime.h>
#include <cuda_bf16.h>
#include <stdint.h>

// LUT_82085414961764: out = a[idx]*d + b[idx], idx = searchsorted(x, d, 'left')
// x sorted, K=1024 breakpoints, a/b have K+1 entries, data 4096x16384 fp32.
//
// Strategy: per-CTA shared-memory acceleration structure.
//   - x_s[1024]          : breakpoints (scan fallback)
//   - ab_s[1025] float2  : interleaved (a,b) for single 64-bit gather
//   - bins_s[8192] u16   : per-bin {start index (15b) | has-breakpoints flag (1b)}
// Query: map d to bin via the SAME monotone float expression used at build time,
// so start is a provably-correct lower bound; short forward scan only when the
// bin contains breakpoints (~28% of lanes). Grid-stride float4 streaming.

#define KMAX 1024
#define NB   8192

__global__ __launch_bounds__(512, 3)
void lut_kernel(const float* __restrict__ data,
                const float* __restrict__ x,
                const float* __restrict__ a,
                const float* __restrict__ b,
                float* __restrict__ out,
                int K, long long n)
{
    __shared__ float  x_s[KMAX];
    __shared__ float2 ab_s[KMAX + 1];
    __shared__ uint16_t bins_s[NB];

    const int tid = threadIdx.x;
    const int bd  = blockDim.x;

    // ---- build phase ----------------------------------------------------
    for (int i = tid; i < K; i += bd)  x_s[i] = x[i];
    for (int i = tid; i <= K; i += bd) ab_s[i] = make_float2(a[i], b[i]);
    __syncthreads();

    const float LO   = x_s[0];
    const float span = x_s[K - 1] - LO;
    const float scale = (span > 0.0f) ? ((float)NB / span) : 0.0f;
    const float NBf = (float)NB;

    // g(v): bin index, monotone non-decreasing in v. Must be IDENTICAL
    // expression at build time and query time. (Plain lambda in device code
    // — no __device__ annotation, bench nvcc lacks --extended-lambda.)
    auto g = [&](float v) -> int {
        float t = (v - LO) * scale;
        if (t < 0.0f) return 0;
        if (t >= NBf) return NB - 1;
        return (int)t;
    };

    // bins_s[bin] = (first i with g(x_s[i]) >= bin) | (flag<<15)
    for (int bin = tid; bin < NB; bin += bd) {
        int lo = 0, hi = K;
        while (lo < hi) {
            int mid = (lo + hi) >> 1;
            if (g(x_s[mid]) < bin) lo = mid + 1; else hi = mid;
        }
        unsigned flag = (lo < K && g(x_s[lo]) == bin) ? 0x8000u : 0u;
        bins_s[bin] = (uint16_t)((unsigned)lo | flag);
    }
    __syncthreads();

    // ---- streaming phase -------------------------------------------------
    auto lut1 = [&](float d) -> float {
        float t = (d - LO) * scale;
        int bin;
        if (t < 0.0f)      bin = 0;
        else if (t >= NBf) bin = NB - 1;
        else               bin = (int)t;
        unsigned v = bins_s[bin];
        int idx = (int)(v & 0x7FFFu);
        if (v & 0x8000u) {
            // forward scan: count breakpoints in this bin that are < d
            while (x_s[idx] < d) {
                ++idx;
                if (idx >= K) break;
            }
        }
        float2 ab = ab_s[idx];
        return fmaf(ab.x, d, ab.y);
    };

    const long long n4 = n >> 2;
    const float4* __restrict__ in4  = (const float4*)data;
    float4* __restrict__       out4 = (float4*)out;
    const long long stride = (long long)gridDim.x * bd;

    for (long long i = (long long)blockIdx.x * bd + tid; i < n4; i += stride) {
        float4 v = in4[i];
        float4 r;
        r.x = lut1(v.x);
        r.y = lut1(v.y);
        r.z = lut1(v.z);
        r.w = lut1(v.w);
        out4[i] = r;
    }

    // tail (n not divisible by 4)
    for (long long i = (n4 << 2) + (long long)blockIdx.x * bd + tid; i < n;
         i += stride) {
        out[i] = lut1(data[i]);
    }
}

extern "C" void kernel_launch(void* const* d_in, const int* in_sizes, int n_in,
                              void* d_out, int out_size)
{
    const float* data = (const float*)d_in[0];
    const float* x    = (const float*)d_in[1];
    const float* a    = (const float*)d_in[2];
    const float* b    = (const float*)d_in[3];
    float* out        = (float*)d_out;

    int K = in_sizes[1];
    if (K > KMAX) K = KMAX;  // problem constant is 1024
    long long n = (long long)out_size;

    const int threads = 512;
    int blocks = 456;  // 3 CTAs per SM on 152 SMs
    long long need = (n / 4 + threads - 1) / threads;
    if ((long long)blocks > need && need > 0) blocks = (int)need;
    if (blocks < 1) blocks = 1;

    lut_kernel<<<blocks, threads>>>(data, x, a, b, out, K, n);
}